// round 2
// baseline (speedup 1.0000x reference)
#include <cuda_runtime.h>
#include <cstdint>

// FilterAugment: out[b,f,t] = x[b,f,t] * 10^(gain_db(b,f)/20)
// B=64, F=256, T=2048 (fp32). Pure HBM stream: 268 MB total traffic.
//
// R2: 8 rows per CTA (2048 CTAs x 256 thr), 16 independent LDG.128 per
// thread for high MLP, .cs streaming hints (zero-reuse data), ~1.7 waves.

#define F_DIM     256
#define T_DIM     2048
#define NBP1      5                 // N_BAND + 1 boundaries
#define ROWS_PER_CTA 8
#define V4_PER_ROW   (T_DIM / 4)    // 512
// log2(10)/20
#define DB_TO_LOG2 0.166096404744368f

__global__ __launch_bounds__(256, 8)
void filter_augment_kernel(const float4* __restrict__ x,
                           const float*  __restrict__ band_factors,
                           const int*    __restrict__ bndry,
                           float4* __restrict__ out)
{
    const int base_row = blockIdx.x * ROWS_PER_CTA;
    const int tid = threadIdx.x;

    // Boundaries (tiny, L1/const-cached)
    int bd[NBP1];
    #pragma unroll
    for (int j = 0; j < NBP1; ++j) bd[j] = __ldg(&bndry[j]);

    // Per-row filter gains for the 8 rows this CTA owns.
    // Every thread computes all 8 redundantly (8x exp2f, trivial vs 16 LDG.128).
    float filt[ROWS_PER_CTA];
    #pragma unroll
    for (int j = 0; j < ROWS_PER_CTA; ++j) {
        const int row = base_row + j;
        const int f = row & (F_DIM - 1);
        const int b = row >> 8;            // F=256

        // searchsorted(bndry, f, 'right') - 1 clipped to [0, NBP1-2]
        int idx = 0;
        #pragma unroll
        for (int k = 1; k < NBP1; ++k)
            idx += (f >= bd[k]) ? 1 : 0;
        if (idx > NBP1 - 2) idx = NBP1 - 2;

        const int lo    = bd[idx];
        const int width = bd[idx + 1] - lo;
        const float denom = (float)max(width - 1, 1);
        const float t = (float)(f - lo) / denom;

        const float g0 = __ldg(&band_factors[b * NBP1 + idx]);
        const float g1 = __ldg(&band_factors[b * NBP1 + idx + 1]);
        const float gain_db = fmaf(g1 - g0, t, g0);
        filt[j] = exp2f(gain_db * DB_TO_LOG2);
    }

    // Stream the 8-row chunk: 8*512 = 4096 float4, 256 threads x 16 iters.
    // Element i*256+tid lies in row (i*256+tid)>>9 = i>>1 (tid < 256) — the
    // row per iteration is compile-time, so filt stays in registers.
    const size_t base4 = (size_t)base_row * V4_PER_ROW;
    const float4* __restrict__ in4  = x   + base4;
    float4* __restrict__       out4 = out + base4;

    #pragma unroll
    for (int i = 0; i < 2 * ROWS_PER_CTA; ++i) {
        const int k = i * 256 + tid;
        const float g = filt[i >> 1];
        float4 v = __ldcs(&in4[k]);       // evict-first: zero reuse
        v.x *= g; v.y *= g; v.z *= g; v.w *= g;
        __stcs(&out4[k], v);
    }
}

extern "C" void kernel_launch(void* const* d_in, const int* in_sizes, int n_in,
                              void* d_out, int out_size)
{
    const float4* features    = (const float4*)d_in[0];
    const float* band_factors = (const float*)d_in[1];
    const int*   bndry        = (const int*)d_in[2];
    float4* out = (float4*)d_out;

    const int B = in_sizes[1] / NBP1;            // band_factors: B*(N_BAND+1)
    const int nrows = B * F_DIM;
    const int nblocks = nrows / ROWS_PER_CTA;    // B*256 always divisible by 8

    filter_augment_kernel<<<nblocks, 256>>>(features, band_factors, bndry, out);
}

// round 3
// speedup vs baseline: 1.1040x; 1.1040x over previous
#include <cuda_runtime.h>
#include <cstdint>

// FilterAugment: out[b,f,t] = x[b,f,t] * 10^(gain_db(b,f)/20)
// B=64, F=256, T=2048 (fp32). Pure HBM stream: 268 MB traffic.
//
// R3: 2 rows per CTA (4096 CTAs x 256 thr), 4 independent LDG.128/thread
// (oe*MLP_p1 = 32, just above Q_th=16 -> minimal cross-CTA L1tex spread),
// ~3.5 waves for work-steal smoothing. Plain cache ops (no .cs — R2's
// confound removed).

#define F_DIM        256
#define T_DIM        2048
#define NBP1         5              // N_BAND + 1 boundaries
#define ROWS_PER_CTA 2
#define V4_PER_ROW   (T_DIM / 4)    // 512
// log2(10)/20
#define DB_TO_LOG2 0.166096404744368f

__global__ __launch_bounds__(256, 8)
void filter_augment_kernel(const float4* __restrict__ x,
                           const float*  __restrict__ band_factors,
                           const int*    __restrict__ bndry,
                           float4* __restrict__ out)
{
    const int base_row = blockIdx.x * ROWS_PER_CTA;
    const int tid = threadIdx.x;

    // Boundaries (tiny, cached)
    int bd[NBP1];
    #pragma unroll
    for (int j = 0; j < NBP1; ++j) bd[j] = __ldg(&bndry[j]);

    // Per-row gains, computed redundantly by every thread (2x exp2f, trivial).
    float filt[ROWS_PER_CTA];
    #pragma unroll
    for (int j = 0; j < ROWS_PER_CTA; ++j) {
        const int row = base_row + j;
        const int f = row & (F_DIM - 1);
        const int b = row >> 8;            // F=256

        // searchsorted(bndry, f, 'right') - 1 clipped to [0, NBP1-2]
        int idx = 0;
        #pragma unroll
        for (int k = 1; k < NBP1; ++k)
            idx += (f >= bd[k]) ? 1 : 0;
        if (idx > NBP1 - 2) idx = NBP1 - 2;

        const int lo    = bd[idx];
        const int width = bd[idx + 1] - lo;
        const float denom = (float)max(width - 1, 1);
        const float t = (float)(f - lo) / denom;

        const float g0 = __ldg(&band_factors[b * NBP1 + idx]);
        const float g1 = __ldg(&band_factors[b * NBP1 + idx + 1]);
        const float gain_db = fmaf(g1 - g0, t, g0);
        filt[j] = exp2f(gain_db * DB_TO_LOG2);
    }

    // Stream 2 rows = 1024 float4: 256 threads x 4 iters.
    // Element i*256+tid is in row i>>1 (tid<256), compile-time constant.
    const size_t base4 = (size_t)base_row * V4_PER_ROW;
    const float4* __restrict__ in4  = x   + base4;
    float4* __restrict__       out4 = out + base4;

    // Batch the 4 loads first (MLP=4), then multiply+store.
    float4 v[4];
    #pragma unroll
    for (int i = 0; i < 4; ++i)
        v[i] = in4[i * 256 + tid];

    #pragma unroll
    for (int i = 0; i < 4; ++i) {
        const float g = filt[i >> 1];
        v[i].x *= g; v[i].y *= g; v[i].z *= g; v[i].w *= g;
        out4[i * 256 + tid] = v[i];
    }
}

extern "C" void kernel_launch(void* const* d_in, const int* in_sizes, int n_in,
                              void* d_out, int out_size)
{
    const float4* features    = (const float4*)d_in[0];
    const float* band_factors = (const float*)d_in[1];
    const int*   bndry        = (const int*)d_in[2];
    float4* out = (float4*)d_out;

    const int B = in_sizes[1] / NBP1;            // band_factors: B*(N_BAND+1)
    const int nrows = B * F_DIM;
    const int nblocks = nrows / ROWS_PER_CTA;

    filter_augment_kernel<<<nblocks, 256>>>(features, band_factors, bndry, out);
}